// round 15
// baseline (speedup 1.0000x reference)
#include <cuda_runtime.h>
#include <math.h>
#include <stdint.h>

#define BB 4096
#define DD 256
#define CC 5994
#define CPAD 6016
#define NTILES 47
#define MTILES 32
#define SCL 30.0f
#define COSM 0.9800665778412416f
#define SINM 0.19866933079506122f
#define EPSC 1e-7f

#define KC 64          // k-chunk per smem stage
#define AST 72         // smem row stride (floats): 8B stride 36 % 16 == 4 -> LDS.64 conflict-free
#define SMEM_DYN (2 * 128 * AST * 4)

typedef unsigned int u32;

__device__ int   g_is64;
__device__ int   g_lab[BB];
__device__ float g_xn[BB * DD];          // normalized x, tf32-rounded, k-permuted in 8-blocks
__device__ float g_wt[CPAD * DD];        // W^T normalized cols, tf32-rounded, k-permuted
__device__ float g_wsum[CPAD];           // column sum-of-squares of W (atomic partials)
__device__ float g_tgt[BB];              // margin logit of the label class per row
__device__ float g_pm[BB * NTILES];      // partial max
__device__ float g_ps[BB * NTILES];      // partial sum
__device__ int   g_pc[BB * NTILES];      // partial argmax (global class)
__device__ float g_accl, g_acch;         // final accumulators
__device__ int   g_done;                 // ticket counter

// k-permutation within each 8-block: (k,k+4) fragment pairs become adjacent.
__device__ __forceinline__ int kperm(int k) {
    return (k & ~7) | ((k & 3) << 1) | ((k & 4) >> 2);
}
__device__ __forceinline__ float to_tf32(float v) {
    u32 u; asm("cvt.rna.tf32.f32 %0, %1;" : "=r"(u) : "f"(v));
    return __uint_as_float(u);
}
__device__ __forceinline__ u32 smem_u32(const void* p) {
    u32 a; asm("{ .reg .u64 t; cvta.to.shared.u64 t, %1; cvt.u32.u64 %0, t; }" : "=r"(a) : "l"(p));
    return a;
}
__device__ __forceinline__ void cp16(u32 saddr, const void* g) {
    asm volatile("cp.async.ca.shared.global [%0], [%1], 16;" :: "r"(saddr), "l"(g));
}

// m16n8k8 tf32 HMMA (baseline sm_80+ PTX)
__device__ __forceinline__ void mma8(float* d, const u32* a, u32 b0, u32 b1) {
    asm volatile(
        "mma.sync.aligned.m16n8k8.row.col.f32.tf32.tf32.f32 "
        "{%0,%1,%2,%3}, {%4,%5,%6,%7}, {%8,%9}, {%0,%1,%2,%3};"
        : "+f"(d[0]), "+f"(d[1]), "+f"(d[2]), "+f"(d[3])
        : "r"(a[0]), "r"(a[1]), "r"(a[2]), "r"(a[3]), "r"(b0), "r"(b1));
}

// ---------------------------------------------------------------------------
// L1: label dtype detection + zero per-replay accumulators
__global__ void detect_kernel(const u32* __restrict__ p) {
    int any = 0;
    for (int i = 1 + 2 * (int)threadIdx.x; i < BB; i += 2 * (int)blockDim.x)
        any |= (p[i] != 0u);
    int r = __syncthreads_or(any);
    if (threadIdx.x == 0) { g_is64 = (r == 0) ? 1 : 0; g_accl = 0.f; g_acch = 0.f; g_done = 0; }
    for (int i = threadIdx.x; i < CPAD; i += blockDim.x) g_wsum[i] = 0.f;
}

// ---------------------------------------------------------------------------
// L2: one grid, three roles by block range.
__global__ void mega_prep(const float* __restrict__ x, const float* __restrict__ W,
                          const int* __restrict__ lab) {
    const int b = blockIdx.x, tid = threadIdx.x;
    if (b < 512) {
        int row = b * 8 + (tid >> 5);
        int lane = tid & 31;
        const float* xr = x + (size_t)row * DD;
        float v[8]; float s = 0.f;
        #pragma unroll
        for (int j = 0; j < 8; j++) { v[j] = xr[lane + 32 * j]; s += v[j] * v[j]; }
        #pragma unroll
        for (int o = 16; o; o >>= 1) s += __shfl_xor_sync(~0u, s, o);
        float inv = 1.0f / fmaxf(sqrtf(s), 1e-12f);
        #pragma unroll
        for (int j = 0; j < 8; j++)
            g_xn[(size_t)row * DD + kperm(lane + 32 * j)] = to_tf32(v[j] * inv);
    } else if (b < 560) {
        int bx = b - 512;
        int cb = (bx >> 2) * 512;
        int k0 = (bx & 3) * 64;
        #pragma unroll
        for (int h = 0; h < 2; h++) {
            int c = cb + h * 256 + tid;
            if (c < CC) {
                float s = 0.f;
                const float* wp = W + (size_t)k0 * CC + c;
                #pragma unroll 8
                for (int k = 0; k < 64; k++) { float v = wp[(size_t)k * CC]; s += v * v; }
                atomicAdd(&g_wsum[c], s);
            }
        }
    } else {
        int i = (b - 560) * 256 + tid;
        if (i < BB) g_lab[i] = g_is64 ? lab[2 * i] : lab[i];
    }
}

// ---------------------------------------------------------------------------
// L3: transpose W -> g_wt [6016, 256], normalize + tf32 round + k-permute.
__global__ void wt_transpose_apply(const float* __restrict__ W) {
    __shared__ float t[32][33];
    int bx = blockIdx.x, by = blockIdx.y;
    int tx = threadIdx.x, ty = threadIdx.y;
    #pragma unroll
    for (int i = ty; i < 32; i += 8) {
        int k = by * 32 + i, c = bx * 32 + tx;
        t[i][tx] = (c < CC) ? W[(size_t)k * CC + c] : 0.f;
    }
    __syncthreads();
    #pragma unroll
    for (int i = ty; i < 32; i += 8) {
        int c = bx * 32 + i;                    // g_wt row = W column
        float inv = 1.0f / fmaxf(sqrtf(g_wsum[c]), 1e-12f);
        g_wt[(size_t)c * DD + kperm(by * 32 + tx)] = to_tf32(t[tx][i] * inv);
    }
}

// ---------------------------------------------------------------------------
// L4 (ncu capture slot): per CTA one (M=128, N=128) tile; mma.sync m16n8k8 tf32.
// Fragment (k,k+4) pairs adjacent in smem -> LDS.64; 24 -> 12 loads per k-step.
__global__ __launch_bounds__(256, 2)
void main_kernel(int dummy) {
    extern __shared__ float sm[];
    float* As = sm;                    // [128][AST]
    float* Bs = sm + 128 * AST;        // [128][AST]
    __shared__ float red_m[128][8], red_s[128][8];
    __shared__ int   red_c[128][8];
    __shared__ int   labs[128];

    const u32 Abase = smem_u32(As), Bbase = smem_u32(Bs);
    const int tid = threadIdx.x, wid = tid >> 5, lane = tid & 31;
    const int gid = lane >> 2, tidg = lane & 3;
    const int mw = wid & 3, nw = wid >> 2;
    const int nt = blockIdx.x, mt = blockIdx.y;
    const int r0 = mt * 128, c0 = nt * 128;

    if (tid < 128) labs[tid] = g_lab[r0 + tid];

    float d[2][8][4];
    #pragma unroll
    for (int tm = 0; tm < 2; tm++)
        #pragma unroll
        for (int tn = 0; tn < 8; tn++)
            #pragma unroll
            for (int c = 0; c < 4; c++) d[tm][tn][c] = 0.f;

    for (int kc = 0; kc < DD; kc += KC) {
        __syncthreads();
        #pragma unroll
        for (int t = 0; t < 8; t++) {
            int i = tid + t * 256;
            int row = i >> 4, f4 = i & 15;
            cp16(Abase + (u32)(row * AST + f4 * 4) * 4,
                 g_xn + (size_t)(r0 + row) * DD + kc + f4 * 4);
            cp16(Bbase + (u32)(row * AST + f4 * 4) * 4,
                 g_wt + (size_t)(c0 + row) * DD + kc + f4 * 4);
        }
        asm volatile("cp.async.commit_group;");
        asm volatile("cp.async.wait_group 0;" ::: "memory");
        __syncthreads();

        #pragma unroll
        for (int ks = 0; ks < KC; ks += 8) {
            const int kf = ks + 2 * tidg;     // permuted: holds (k, k+4)
            u32 a[2][4];
            #pragma unroll
            for (int tm = 0; tm < 2; tm++) {
                int rb = mw * 32 + tm * 16 + gid;
                float2 alo = *(const float2*)&As[rb * AST + kf];        // (a0,a2)
                float2 ahi = *(const float2*)&As[(rb + 8) * AST + kf];  // (a1,a3)
                a[tm][0] = __float_as_uint(alo.x);
                a[tm][1] = __float_as_uint(ahi.x);
                a[tm][2] = __float_as_uint(alo.y);
                a[tm][3] = __float_as_uint(ahi.y);
            }
            #pragma unroll
            for (int tn = 0; tn < 8; tn++) {
                int nb = nw * 64 + tn * 8 + gid;
                float2 bv = *(const float2*)&Bs[nb * AST + kf];         // (b0,b1)
                u32 b0 = __float_as_uint(bv.x);
                u32 b1 = __float_as_uint(bv.y);
                mma8(d[0][tn], a[0], b0, b1);
                mma8(d[1][tn], a[1], b0, b1);
            }
        }
    }

    // Epilogue: thread owns rows {mw*32 + tm*16 + rh*8 + gid}, 16 cols each.
    #pragma unroll
    for (int tm = 0; tm < 2; tm++) {
        #pragma unroll
        for (int rh = 0; rh < 2; rh++) {
            int rloc = mw * 32 + tm * 16 + rh * 8 + gid;
            int rg = r0 + rloc;
            int lab = labs[rloc];
            float m = -INFINITY, s = 0.f; int bc = 0x7fffffff;
            #pragma unroll
            for (int tn = 0; tn < 8; tn++) {
                #pragma unroll
                for (int c = 0; c < 2; c++) {
                    int cg = c0 + nw * 64 + tn * 8 + 2 * tidg + c;
                    if (cg < CC) {
                        float ct = fminf(fmaxf(d[tm][tn][rh * 2 + c], -1.0f + EPSC), 1.0f + EPSC);
                        float lg;
                        if (cg == lab) {
                            float s2 = 1.0f - ct * ct;
                            float sn = (s2 > 0.f) ? sqrtf(s2) : 0.f;
                            lg = (ct * COSM - sn * SINM) * SCL;
                            g_tgt[rg] = lg;
                        } else {
                            lg = ct * SCL;
                        }
                        if (lg > m) { s = s * __expf(m - lg) + 1.0f; m = lg; bc = cg; }
                        else        { s += __expf(lg - m); }
                    }
                }
            }
            int slot = nw * 4 + tidg;
            red_m[rloc][slot] = m; red_s[rloc][slot] = s; red_c[rloc][slot] = bc;
        }
    }
    __syncthreads();

    if (tid < 128) {
        const int rloc = tid, rg = r0 + rloc;
        float m = red_m[rloc][0], s = red_s[rloc][0]; int c = red_c[rloc][0];
        #pragma unroll
        for (int w = 1; w < 8; w++) {
            float om = red_m[rloc][w], os = red_s[rloc][w]; int oc = red_c[rloc][w];
            float M = fmaxf(m, om);
            s = s * __expf(m - M) + os * __expf(om - M);
            if (om > m) c = oc;
            m = M;
        }
        g_pm[(size_t)rg * NTILES + nt] = m;
        g_ps[(size_t)rg * NTILES + nt] = s;
        g_pc[(size_t)rg * NTILES + nt] = c;
    }
}

// ---------------------------------------------------------------------------
// L5: combine tile partials -> per-row loss/hit -> atomic accumulate -> ticket.
__global__ void combine_final(float* __restrict__ out) {
    __shared__ float sl[128], sh[128];
    const int tid = threadIdx.x;
    const int r = blockIdx.x * 128 + tid;

    float m = -INFINITY, s = 0.f; int c = 0x7fffffff;
    for (int j = 0; j < NTILES; j++) {
        float pm = g_pm[(size_t)r * NTILES + j];
        float ps = g_ps[(size_t)r * NTILES + j];
        int   pc = g_pc[(size_t)r * NTILES + j];
        float M = fmaxf(m, pm);
        s = s * __expf(m - M) + ps * __expf(pm - M);
        if (pm > m) c = pc;                 // ascending j => lowest class on tie
        m = M;
    }
    sl[tid] = (m + logf(s)) - g_tgt[r];
    sh[tid] = (c == g_lab[r]) ? 1.0f : 0.0f;
    __syncthreads();
    for (int o = 64; o; o >>= 1) {
        if (tid < o) { sl[tid] += sl[tid + o]; sh[tid] += sh[tid + o]; }
        __syncthreads();
    }
    if (tid == 0) {
        atomicAdd(&g_accl, sl[0]);
        atomicAdd(&g_acch, sh[0]);
        __threadfence();
        int ticket = atomicAdd(&g_done, 1);
        if (ticket == (int)gridDim.x - 1) {
            float l = atomicAdd(&g_accl, 0.f);
            float h = atomicAdd(&g_acch, 0.f);
            out[0] = l / (float)BB;
            out[1] = h * (100.0f / (float)BB);
        }
    }
}

// ---------------------------------------------------------------------------
extern "C" void kernel_launch(void* const* d_in, const int* in_sizes, int n_in,
                              void* d_out, int out_size) {
    const float* x   = (const float*)d_in[0];
    const float* W   = (const float*)d_in[1];
    const int*   lab = (const int*)d_in[2];

    cudaFuncSetAttribute(main_kernel, cudaFuncAttributeMaxDynamicSharedMemorySize, SMEM_DYN);

    detect_kernel<<<1, 256>>>((const u32*)lab);                  // 1
    mega_prep<<<576, 256>>>(x, W, lab);                          // 2
    wt_transpose_apply<<<dim3(188, 8), dim3(32, 8)>>>(W);        // 3
    main_kernel<<<dim3(NTILES, MTILES), 256, SMEM_DYN>>>(0);     // 4  <- ncu capture slot
    combine_final<<<32, 128>>>((float*)d_out);                   // 5
}